// round 1
// baseline (speedup 1.0000x reference)
#include <cuda_runtime.h>
#include <cuda_bf16.h>

#define BATCH      256
#define INPUT_DIM  4096
#define SOMA       2048
#define BRANCH     16
#define NUM_DEND   (SOMA * BRANCH)   // 32768
#define SAMPLE     32
#define NEG        0.1f

#define BT         8                 // batches per block (interleaved in smem)
#define DT         512               // dendrites per block (= threads)
#define NTHREADS   512

// smem: xs_lo[4096] float4 (batches 0..3), xs_hi[4096] float4 (batches 4..7) = 128KB
__global__ __launch_bounds__(NTHREADS, 1)
void dend_kernel(const float* __restrict__ x,
                 const int*   __restrict__ idx,
                 const float* __restrict__ sw,
                 const float* __restrict__ sb,
                 const float* __restrict__ cw,
                 const float* __restrict__ somab,
                 float* __restrict__ soma_out,
                 float* __restrict__ dend_out)
{
    extern __shared__ float4 xs[];
    float4* xs_lo = xs;
    float4* xs_hi = xs + INPUT_DIM;

    const int b0  = blockIdx.y * BT;
    const int d0  = blockIdx.x * DT;
    const int tid = threadIdx.x;

    // Stage 8 x rows into smem, batch-interleaved (float4 lo = b0..b0+3, hi = b0+4..b0+7)
    const float* xr = x + (size_t)b0 * INPUT_DIM;
    for (int i = tid; i < INPUT_DIM; i += NTHREADS) {
        float4 lo, hi;
        lo.x = xr[0 * INPUT_DIM + i];
        lo.y = xr[1 * INPUT_DIM + i];
        lo.z = xr[2 * INPUT_DIM + i];
        lo.w = xr[3 * INPUT_DIM + i];
        hi.x = xr[4 * INPUT_DIM + i];
        hi.y = xr[5 * INPUT_DIM + i];
        hi.z = xr[6 * INPUT_DIM + i];
        hi.w = xr[7 * INPUT_DIM + i];
        xs_lo[i] = lo;
        xs_hi[i] = hi;
    }
    __syncthreads();

    const int d = d0 + tid;
    const int4*   idx4 = (const int4*)  (idx + (size_t)d * SAMPLE);
    const float4* wv4  = (const float4*)(sw  + (size_t)d * SAMPLE);

    float acc0 = 0.f, acc1 = 0.f, acc2 = 0.f, acc3 = 0.f;
    float acc4 = 0.f, acc5 = 0.f, acc6 = 0.f, acc7 = 0.f;

    #pragma unroll
    for (int s4 = 0; s4 < SAMPLE / 4; ++s4) {
        const int4   i4 = idx4[s4];
        const float4 wv = wv4[s4];

        {   const float4 a = xs_lo[i4.x]; const float4 b = xs_hi[i4.x]; const float w = wv.x;
            acc0 = fmaf(w, a.x, acc0); acc1 = fmaf(w, a.y, acc1);
            acc2 = fmaf(w, a.z, acc2); acc3 = fmaf(w, a.w, acc3);
            acc4 = fmaf(w, b.x, acc4); acc5 = fmaf(w, b.y, acc5);
            acc6 = fmaf(w, b.z, acc6); acc7 = fmaf(w, b.w, acc7); }
        {   const float4 a = xs_lo[i4.y]; const float4 b = xs_hi[i4.y]; const float w = wv.y;
            acc0 = fmaf(w, a.x, acc0); acc1 = fmaf(w, a.y, acc1);
            acc2 = fmaf(w, a.z, acc2); acc3 = fmaf(w, a.w, acc3);
            acc4 = fmaf(w, b.x, acc4); acc5 = fmaf(w, b.y, acc5);
            acc6 = fmaf(w, b.z, acc6); acc7 = fmaf(w, b.w, acc7); }
        {   const float4 a = xs_lo[i4.z]; const float4 b = xs_hi[i4.z]; const float w = wv.z;
            acc0 = fmaf(w, a.x, acc0); acc1 = fmaf(w, a.y, acc1);
            acc2 = fmaf(w, a.z, acc2); acc3 = fmaf(w, a.w, acc3);
            acc4 = fmaf(w, b.x, acc4); acc5 = fmaf(w, b.y, acc5);
            acc6 = fmaf(w, b.z, acc6); acc7 = fmaf(w, b.w, acc7); }
        {   const float4 a = xs_lo[i4.w]; const float4 b = xs_hi[i4.w]; const float w = wv.w;
            acc0 = fmaf(w, a.x, acc0); acc1 = fmaf(w, a.y, acc1);
            acc2 = fmaf(w, a.z, acc2); acc3 = fmaf(w, a.w, acc3);
            acc4 = fmaf(w, b.x, acc4); acc5 = fmaf(w, b.y, acc5);
            acc6 = fmaf(w, b.z, acc6); acc7 = fmaf(w, b.w, acc7); }
    }

    const float bias = sb[d];
    const float cwv  = cw[d];   // cable_weights flattened [soma][branch] == index d

    float sv[BT];
    float accs[BT] = {acc0, acc1, acc2, acc3, acc4, acc5, acc6, acc7};
    #pragma unroll
    for (int j = 0; j < BT; ++j) {
        float p = accs[j] + bias;
        float a = p >= 0.f ? p : NEG * p;
        dend_out[(size_t)(b0 + j) * NUM_DEND + d] = a;
        sv[j] = a * cwv;
    }

    // Segmented reduction over the 16 branches (16 consecutive lanes)
    #pragma unroll
    for (int off = 8; off >= 1; off >>= 1) {
        #pragma unroll
        for (int j = 0; j < BT; ++j)
            sv[j] += __shfl_xor_sync(0xffffffffu, sv[j], off);
    }

    if ((tid & (BRANCH - 1)) == 0) {
        const int n  = d >> 4;
        const float nb = somab[n];
        #pragma unroll
        for (int j = 0; j < BT; ++j) {
            float p = sv[j] + nb;
            soma_out[(size_t)(b0 + j) * SOMA + n] = p >= 0.f ? p : NEG * p;
        }
    }
}

extern "C" void kernel_launch(void* const* d_in, const int* in_sizes, int n_in,
                              void* d_out, int out_size)
{
    const float* x     = (const float*)d_in[0];
    const int*   idx   = (const int*)  d_in[1];
    const float* sw    = (const float*)d_in[2];
    const float* sb    = (const float*)d_in[3];
    const float* cw    = (const float*)d_in[4];
    const float* somab = (const float*)d_in[5];

    float* out      = (float*)d_out;
    float* soma_out = out;                          // [256, 2048]
    float* dend_out = out + (size_t)BATCH * SOMA;   // [256, 32768]

    const size_t smem = 2 * INPUT_DIM * sizeof(float4);  // 128 KB
    cudaFuncSetAttribute(dend_kernel, cudaFuncAttributeMaxDynamicSharedMemorySize, (int)smem);

    dim3 grid(NUM_DEND / DT, BATCH / BT);
    dend_kernel<<<grid, NTHREADS, smem>>>(x, idx, sw, sb, cw, somab, soma_out, dend_out);
}